// round 2
// baseline (speedup 1.0000x reference)
#include <cuda_runtime.h>

#define NN 10000
#define NE 320000
#define NF4 (NN * 32)   // N * 128 floats / 4

// ---- device scratch (allocation-free rule: __device__ globals) ----
__device__ int    g_cnt[NN];
__device__ int    g_cursor[NN];
__device__ int    g_rowptr[NN + 1];
__device__ float  g_dinv[NN];
__device__ int    g_src[NE];
__device__ float  g_wgt[NE];
__device__ float4 g_cur[2][NF4];
__device__ float4 g_upd[NF4];
__device__ float  g_tk[8];
__device__ float  g_cst[1];

// ---- init: cur0 = x, upd = 0, counters = 0 ----
__global__ void k_init(const float4* __restrict__ x4) {
    int i = blockIdx.x * blockDim.x + threadIdx.x;
    if (i < NF4) {
        g_cur[0][i] = x4[i];
        g_upd[i] = make_float4(0.f, 0.f, 0.f, 0.f);
    }
    if (i < NN) { g_cnt[i] = 0; g_cursor[i] = 0; }
}

// ---- degree count over targets (col) ----  edge_index is INT32 [2, NE]
__global__ void k_count(const int* __restrict__ ei) {
    int e = blockIdx.x * blockDim.x + threadIdx.x;
    if (e < NE) atomicAdd(&g_cnt[ei[NE + e]], 1);
}

// ---- dinv = deg^-1/2 (0 -> 1); also scalar prep ----
__global__ void k_dinv(const float* __restrict__ kv, const float* __restrict__ wt) {
    int n = blockIdx.x * blockDim.x + threadIdx.x;
    if (n < NN) {
        int c = g_cnt[n];
        g_dinv[n] = rsqrtf((float)(c ? c : 1));
    }
    if (n < 8)  g_tk[n] = tanhf(kv[n]);
    if (n == 8) g_cst[0] = 1.f / (1.f + expf(-wt[0]));
}

// ---- exclusive scan of counts -> rowptr (single block, 1024 threads) ----
__global__ void k_scan() {
    __shared__ int sh[1024];
    __shared__ int carry;
    int tid = threadIdx.x;
    if (tid == 0) carry = 0;
    __syncthreads();
    for (int base = 0; base < NN; base += 1024) {
        int i = base + tid;
        int v = (i < NN) ? g_cnt[i] : 0;
        sh[tid] = v;
        __syncthreads();
        for (int off = 1; off < 1024; off <<= 1) {
            int t = (tid >= off) ? sh[tid - off] : 0;
            __syncthreads();
            sh[tid] += t;
            __syncthreads();
        }
        if (i < NN) g_rowptr[i] = carry + sh[tid] - v;
        __syncthreads();
        if (tid == 0) carry += sh[1023];
        __syncthreads();
    }
    if (tid == 0) g_rowptr[NN] = carry;
}

// ---- fill CSR buckets: edges grouped by target node ----
__global__ void k_fill(const int* __restrict__ ei) {
    int e = blockIdx.x * blockDim.x + threadIdx.x;
    if (e < NE) {
        int r = ei[e];
        int c = ei[NE + e];
        int pos = g_rowptr[c] + atomicAdd(&g_cursor[c], 1);
        g_src[pos] = r;
        g_wgt[pos] = g_dinv[r] * g_dinv[c];
    }
}

// ---- one propagation layer: warp-per-node pull gather, no atomics ----
__global__ void __launch_bounds__(256) k_layer(int parity, int layer) {
    int gw   = (blockIdx.x * blockDim.x + threadIdx.x) >> 5;  // node id
    int lane = threadIdx.x & 31;
    if (gw >= NN) return;
    const float4* __restrict__ cin  = g_cur[parity];
    float4* __restrict__       cout = g_cur[parity ^ 1];

    int beg = g_rowptr[gw], end = g_rowptr[gw + 1];
    float ax = 0.f, ay = 0.f, az = 0.f, aw = 0.f;

    int e = beg;
    // unroll x4 for MLP against L2 gather latency
    for (; e + 3 < end; e += 4) {
        int s0 = g_src[e], s1 = g_src[e + 1], s2 = g_src[e + 2], s3 = g_src[e + 3];
        float w0 = g_wgt[e], w1 = g_wgt[e + 1], w2 = g_wgt[e + 2], w3 = g_wgt[e + 3];
        float4 v0 = cin[s0 * 32 + lane];
        float4 v1 = cin[s1 * 32 + lane];
        float4 v2 = cin[s2 * 32 + lane];
        float4 v3 = cin[s3 * 32 + lane];
        ax = fmaf(w0, v0.x, ax); ay = fmaf(w0, v0.y, ay);
        az = fmaf(w0, v0.z, az); aw = fmaf(w0, v0.w, aw);
        ax = fmaf(w1, v1.x, ax); ay = fmaf(w1, v1.y, ay);
        az = fmaf(w1, v1.z, az); aw = fmaf(w1, v1.w, aw);
        ax = fmaf(w2, v2.x, ax); ay = fmaf(w2, v2.y, ay);
        az = fmaf(w2, v2.z, az); aw = fmaf(w2, v2.w, aw);
        ax = fmaf(w3, v3.x, ax); ay = fmaf(w3, v3.y, ay);
        az = fmaf(w3, v3.z, az); aw = fmaf(w3, v3.w, aw);
    }
    for (; e < end; e++) {
        int s = g_src[e];
        float w = g_wgt[e];
        float4 v = cin[s * 32 + lane];
        ax = fmaf(w, v.x, ax); ay = fmaf(w, v.y, ay);
        az = fmaf(w, v.z, az); aw = fmaf(w, v.w, aw);
    }

    float4 cv = cin[gw * 32 + lane];
    float4 o = make_float4(cv.x - ax, cv.y - ay, cv.z - az, cv.w - aw);
    cout[gw * 32 + lane] = o;

    float tk = g_tk[layer];
    float4 u = g_upd[gw * 32 + lane];
    u.x = fmaf(tk, o.x, u.x); u.y = fmaf(tk, o.y, u.y);
    u.z = fmaf(tk, o.z, u.z); u.w = fmaf(tk, o.w, u.w);
    g_upd[gw * 32 + lane] = u;
}

// ---- epilogue: h = c*upd + (1-c)*x ; out = relu(h @ W^T + b) ----
// Tiled GEMM: BM=64 nodes, BN=64 outputs, BK=32, 4x4 register tile, 256 thr.
__global__ void __launch_bounds__(256) k_out(const float4* __restrict__ x4,
                                             const float4* __restrict__ W4,
                                             const float*  __restrict__ bias,
                                             float*        __restrict__ out) {
    __shared__ float sA[32][68];  // [k][m]
    __shared__ float sB[32][68];  // [k][j]
    int mblk = blockIdx.x * 64;
    int nblk = blockIdx.y * 64;
    int tid = threadIdx.x;
    int tx = tid & 15, ty = tid >> 4;

    float c = g_cst[0], d = 1.f - c;
    float acc[4][4];
#pragma unroll
    for (int i = 0; i < 4; i++)
#pragma unroll
        for (int j = 0; j < 4; j++) acc[i][j] = 0.f;

    for (int k0 = 0; k0 < 128; k0 += 32) {
#pragma unroll
        for (int l = 0; l < 2; l++) {
            int idx = tid + l * 256;   // 0..511 float4 slots
            int m  = idx >> 3;         // row within tile (0..63)
            int kq = idx & 7;          // float4 within 32-wide k tile
            int kk = kq * 4;
            // A = h tile (computed on the fly)
            int node = mblk + m;
            float4 u  = make_float4(0.f, 0.f, 0.f, 0.f), xv = u;
            if (node < NN) {
                int off = node * 32 + (k0 >> 2) + kq;
                u  = g_upd[off];
                xv = x4[off];
            }
            sA[kk + 0][m] = c * u.x + d * xv.x;
            sA[kk + 1][m] = c * u.y + d * xv.y;
            sA[kk + 2][m] = c * u.z + d * xv.z;
            sA[kk + 3][m] = c * u.w + d * xv.w;
            // B = W tile (W row-major [j][f], f contiguous)
            float4 wv = W4[(nblk + m) * 32 + (k0 >> 2) + kq];
            sB[kk + 0][m] = wv.x;
            sB[kk + 1][m] = wv.y;
            sB[kk + 2][m] = wv.z;
            sB[kk + 3][m] = wv.w;
        }
        __syncthreads();
#pragma unroll
        for (int kk = 0; kk < 32; kk++) {
            float a[4], bb[4];
#pragma unroll
            for (int i = 0; i < 4; i++) a[i] = sA[kk][ty * 4 + i];
#pragma unroll
            for (int j = 0; j < 4; j++) bb[j] = sB[kk][tx * 4 + j];
#pragma unroll
            for (int i = 0; i < 4; i++)
#pragma unroll
                for (int j = 0; j < 4; j++)
                    acc[i][j] = fmaf(a[i], bb[j], acc[i][j]);
        }
        __syncthreads();
    }

#pragma unroll
    for (int i = 0; i < 4; i++) {
        int node = mblk + ty * 4 + i;
        if (node >= NN) continue;
#pragma unroll
        for (int j = 0; j < 4; j++) {
            int jj = nblk + tx * 4 + j;
            float v = acc[i][j] + bias[jj];
            out[node * 128 + jj] = v > 0.f ? v : 0.f;
        }
    }
}

extern "C" void kernel_launch(void* const* d_in, const int* in_sizes, int n_in,
                              void* d_out, int out_size) {
    const float4* x4   = (const float4*)d_in[0];
    const int*    ei   = (const int*)d_in[1];       // int32 [2, NE] (JAX default x64-off)
    const float*  kv   = (const float*)d_in[2];
    const float*  wt   = (const float*)d_in[3];
    const float4* W4   = (const float4*)d_in[4];
    const float*  bias = (const float*)d_in[5];
    float*        out  = (float*)d_out;

    k_init<<<(NF4 + 255) / 256, 256>>>(x4);
    k_count<<<(NE + 255) / 256, 256>>>(ei);
    k_dinv<<<(NN + 255) / 256, 256>>>(kv, wt);
    k_scan<<<1, 1024>>>();
    k_fill<<<(NE + 255) / 256, 256>>>(ei);

    int par = 0;
    for (int l = 0; l < 8; l++) {
        k_layer<<<(NN * 32 + 255) / 256, 256>>>(par, l);
        par ^= 1;
    }

    dim3 g((NN + 63) / 64, 2);
    k_out<<<g, 256>>>(x4, W4, bias, out);
}

// round 4
// speedup vs baseline: 1.0828x; 1.0828x over previous
#include <cuda_runtime.h>

#define NN 10000
#define NE 320000
#define NF4 (NN * 32)   // N * 128 floats / 4

// ---- device scratch (allocation-free rule: __device__ globals) ----
__device__ int    g_cnt[NN];
__device__ int    g_cursor[NN];
__device__ int    g_beg[NN];      // bucket start per target (NOT monotone; just a partition)
__device__ int    g_total;
__device__ float  g_dinv[NN];
__device__ int    g_src[NE];
__device__ float  g_wgt[NE];
__device__ float4 g_cur[2][NF4];
__device__ float4 g_upd[NF4];
__device__ float  g_tk[8];
__device__ float  g_cst[1];

// ---- init: cur0 = x, counters = 0 ----
__global__ void k_init(const float4* __restrict__ x4) {
    int i = blockIdx.x * blockDim.x + threadIdx.x;
    if (i < NF4) g_cur[0][i] = x4[i];
    if (i < NN) { g_cnt[i] = 0; g_cursor[i] = 0; }
    if (i == 0) g_total = 0;
}

// ---- degree count over targets (col) ----  edge_index is INT32 [2, NE]
__global__ void k_count(const int* __restrict__ ei) {
    int e = blockIdx.x * blockDim.x + threadIdx.x;
    if (e < NE) atomicAdd(&g_cnt[ei[NE + e]], 1);
}

// ---- dinv = deg^-1/2 (0 -> 1); bucket allocation; scalar prep ----
__global__ void k_dinv(const float* __restrict__ kv, const float* __restrict__ wt) {
    int n = blockIdx.x * blockDim.x + threadIdx.x;
    if (n < NN) {
        int c = g_cnt[n];
        g_dinv[n] = rsqrtf((float)(c ? c : 1));
        g_beg[n] = atomicAdd(&g_total, c);   // contiguous bucket, any order
    }
    if (n < 8)  g_tk[n] = tanhf(kv[n]);
    if (n == 8) g_cst[0] = 1.f / (1.f + expf(-wt[0]));
}

// ---- fill CSR buckets: edges grouped by target node ----
__global__ void k_fill(const int* __restrict__ ei) {
    int e = blockIdx.x * blockDim.x + threadIdx.x;
    if (e < NE) {
        int r = ei[e];
        int c = ei[NE + e];
        int pos = g_beg[c] + atomicAdd(&g_cursor[c], 1);
        g_src[pos] = r;
        g_wgt[pos] = g_dinv[r] * g_dinv[c];
    }
}

// ---- one propagation layer: warp-per-node pull gather, no atomics ----
// first: upd = tk*o (skip zero read). write_cur=0 on last layer (dead store).
__global__ void __launch_bounds__(256) k_layer(int parity, int layer,
                                               int first, int write_cur) {
    int gw   = (blockIdx.x * blockDim.x + threadIdx.x) >> 5;  // node id
    int lane = threadIdx.x & 31;
    if (gw >= NN) return;
    const float4* __restrict__ cin  = g_cur[parity];
    float4* __restrict__       cout = g_cur[parity ^ 1];

    int beg = g_beg[gw];
    int end = beg + g_cnt[gw];
    float ax = 0.f, ay = 0.f, az = 0.f, aw = 0.f;

    int e = beg;
    for (; e + 3 < end; e += 4) {
        int s0 = g_src[e], s1 = g_src[e + 1], s2 = g_src[e + 2], s3 = g_src[e + 3];
        float w0 = g_wgt[e], w1 = g_wgt[e + 1], w2 = g_wgt[e + 2], w3 = g_wgt[e + 3];
        float4 v0 = cin[s0 * 32 + lane];
        float4 v1 = cin[s1 * 32 + lane];
        float4 v2 = cin[s2 * 32 + lane];
        float4 v3 = cin[s3 * 32 + lane];
        ax = fmaf(w0, v0.x, ax); ay = fmaf(w0, v0.y, ay);
        az = fmaf(w0, v0.z, az); aw = fmaf(w0, v0.w, aw);
        ax = fmaf(w1, v1.x, ax); ay = fmaf(w1, v1.y, ay);
        az = fmaf(w1, v1.z, az); aw = fmaf(w1, v1.w, aw);
        ax = fmaf(w2, v2.x, ax); ay = fmaf(w2, v2.y, ay);
        az = fmaf(w2, v2.z, az); aw = fmaf(w2, v2.w, aw);
        ax = fmaf(w3, v3.x, ax); ay = fmaf(w3, v3.y, ay);
        az = fmaf(w3, v3.z, az); aw = fmaf(w3, v3.w, aw);
    }
    for (; e < end; e++) {
        int s = g_src[e];
        float w = g_wgt[e];
        float4 v = cin[s * 32 + lane];
        ax = fmaf(w, v.x, ax); ay = fmaf(w, v.y, ay);
        az = fmaf(w, v.z, az); aw = fmaf(w, v.w, aw);
    }

    int off = gw * 32 + lane;
    float4 cv = cin[off];
    float4 o = make_float4(cv.x - ax, cv.y - ay, cv.z - az, cv.w - aw);
    if (write_cur) cout[off] = o;

    float tk = g_tk[layer];
    if (first) {
        g_upd[off] = make_float4(tk * o.x, tk * o.y, tk * o.z, tk * o.w);
    } else {
        float4 u = g_upd[off];
        u.x = fmaf(tk, o.x, u.x); u.y = fmaf(tk, o.y, u.y);
        u.z = fmaf(tk, o.z, u.z); u.w = fmaf(tk, o.w, u.w);
        g_upd[off] = u;
    }
}

// ---- epilogue: h = c*upd + (1-c)*x ; out = relu(h @ W^T + b) ----
// Tiled GEMM: BM=64 nodes, BN=64 outputs, BK=32, 4x4 register tile, 256 thr.
__global__ void __launch_bounds__(256) k_out(const float4* __restrict__ x4,
                                             const float4* __restrict__ W4,
                                             const float*  __restrict__ bias,
                                             float*        __restrict__ out) {
    __shared__ float sA[32][68];  // [k][m]
    __shared__ float sB[32][68];  // [k][j]
    int mblk = blockIdx.x * 64;
    int nblk = blockIdx.y * 64;
    int tid = threadIdx.x;
    int tx = tid & 15, ty = tid >> 4;

    float c = g_cst[0], d = 1.f - c;
    float acc[4][4];
#pragma unroll
    for (int i = 0; i < 4; i++)
#pragma unroll
        for (int j = 0; j < 4; j++) acc[i][j] = 0.f;

    for (int k0 = 0; k0 < 128; k0 += 32) {
#pragma unroll
        for (int l = 0; l < 2; l++) {
            int idx = tid + l * 256;   // 0..511 float4 slots
            int m  = idx >> 3;         // row within tile (0..63)
            int kq = idx & 7;          // float4 within 32-wide k tile
            int kk = kq * 4;
            int node = mblk + m;
            float4 u  = make_float4(0.f, 0.f, 0.f, 0.f), xv = u;
            if (node < NN) {
                int off = node * 32 + (k0 >> 2) + kq;
                u  = g_upd[off];
                xv = x4[off];
            }
            sA[kk + 0][m] = c * u.x + d * xv.x;
            sA[kk + 1][m] = c * u.y + d * xv.y;
            sA[kk + 2][m] = c * u.z + d * xv.z;
            sA[kk + 3][m] = c * u.w + d * xv.w;
            float4 wv = W4[(nblk + m) * 32 + (k0 >> 2) + kq];
            sB[kk + 0][m] = wv.x;
            sB[kk + 1][m] = wv.y;
            sB[kk + 2][m] = wv.z;
            sB[kk + 3][m] = wv.w;
        }
        __syncthreads();
#pragma unroll
        for (int kk = 0; kk < 32; kk++) {
            float a[4], bb[4];
#pragma unroll
            for (int i = 0; i < 4; i++) a[i] = sA[kk][ty * 4 + i];
#pragma unroll
            for (int j = 0; j < 4; j++) bb[j] = sB[kk][tx * 4 + j];
#pragma unroll
            for (int i = 0; i < 4; i++)
#pragma unroll
                for (int j = 0; j < 4; j++)
                    acc[i][j] = fmaf(a[i], bb[j], acc[i][j]);
        }
        __syncthreads();
    }

#pragma unroll
    for (int i = 0; i < 4; i++) {
        int node = mblk + ty * 4 + i;
        if (node >= NN) continue;
#pragma unroll
        for (int j = 0; j < 4; j++) {
            int jj = nblk + tx * 4 + j;
            float v = acc[i][j] + bias[jj];
            out[node * 128 + jj] = v > 0.f ? v : 0.f;
        }
    }
}

extern "C" void kernel_launch(void* const* d_in, const int* in_sizes, int n_in,
                              void* d_out, int out_size) {
    const float4* x4   = (const float4*)d_in[0];
    const int*    ei   = (const int*)d_in[1];       // int32 [2, NE]
    const float*  kv   = (const float*)d_in[2];
    const float*  wt   = (const float*)d_in[3];
    const float4* W4   = (const float4*)d_in[4];
    const float*  bias = (const float*)d_in[5];
    float*        out  = (float*)d_out;

    k_init<<<(NF4 + 255) / 256, 256>>>(x4);
    k_count<<<(NE + 255) / 256, 256>>>(ei);
    k_dinv<<<(NN + 255) / 256, 256>>>(kv, wt);
    k_fill<<<(NE + 255) / 256, 256>>>(ei);

    int par = 0;
    for (int l = 0; l < 8; l++) {
        k_layer<<<(NN * 32 + 255) / 256, 256>>>(par, l, l == 0, l != 7);
        par ^= 1;
    }

    dim3 g((NN + 63) / 64, 2);
    k_out<<<g, 256>>>(x4, W4, bias, out);
}

// round 5
// speedup vs baseline: 1.2836x; 1.1854x over previous
#include <cuda_runtime.h>
#include <cuda_fp16.h>

#define NN 10000
#define NE 320000
#define NF4 (NN * 32)   // N * 128 floats / 4

// ---- device scratch ----
__device__ int    g_cnt[NN];
__device__ int    g_cursor[NN];
__device__ int    g_beg[NN];
__device__ int    g_total;
__device__ float  g_dinv[NN];
__device__ int    g_src[NE];
__device__ float  g_wgt[NE];
__device__ float4 g_cur[2][NF4];   // fp32 carry (exact path)
__device__ uint2  g_curh[2][NF4];  // fp16 mirror (gather path): 4 halves per lane
__device__ float4 g_upd[NF4];
__device__ float  g_tk[8];
__device__ float  g_cst[1];

static __device__ __forceinline__ uint2 pack4h(float a, float b, float c, float d) {
    __half2 lo = __floats2half2_rn(a, b);
    __half2 hi = __floats2half2_rn(c, d);
    uint2 r;
    r.x = *reinterpret_cast<unsigned*>(&lo);
    r.y = *reinterpret_cast<unsigned*>(&hi);
    return r;
}

// ---- init: cur0 = x (fp32 + fp16 mirror), counters = 0 ----
__global__ void k_init(const float4* __restrict__ x4) {
    int i = blockIdx.x * blockDim.x + threadIdx.x;
    if (i < NF4) {
        float4 v = x4[i];
        g_cur[0][i] = v;
        g_curh[0][i] = pack4h(v.x, v.y, v.z, v.w);
    }
    if (i < NN) { g_cnt[i] = 0; g_cursor[i] = 0; }
    if (i == 0) g_total = 0;
}

// ---- degree count over targets: 4 edges/thread for atomic ILP ----
__global__ void k_count(const int* __restrict__ ei) {
    int t = blockIdx.x * blockDim.x + threadIdx.x;
    int e = t * 4;
    if (e + 3 < NE) {
        int4 c4 = *reinterpret_cast<const int4*>(ei + NE + e);
        atomicAdd(&g_cnt[c4.x], 1);
        atomicAdd(&g_cnt[c4.y], 1);
        atomicAdd(&g_cnt[c4.z], 1);
        atomicAdd(&g_cnt[c4.w], 1);
    } else {
        for (; e < NE; e++) atomicAdd(&g_cnt[ei[NE + e]], 1);
    }
}

// ---- dinv = deg^-1/2 (0 -> 1); bucket allocation; scalar prep ----
__global__ void k_dinv(const float* __restrict__ kv, const float* __restrict__ wt) {
    int n = blockIdx.x * blockDim.x + threadIdx.x;
    if (n < NN) {
        int c = g_cnt[n];
        g_dinv[n] = rsqrtf((float)(c ? c : 1));
        g_beg[n] = atomicAdd(&g_total, c);
    }
    if (n < 8)  g_tk[n] = tanhf(kv[n]);
    if (n == 8) g_cst[0] = 1.f / (1.f + expf(-wt[0]));
}

// ---- fill CSR buckets: 4 edges/thread for atomic ILP ----
__global__ void k_fill(const int* __restrict__ ei) {
    int t = blockIdx.x * blockDim.x + threadIdx.x;
    int e = t * 4;
    if (e + 3 < NE) {
        int4 r4 = *reinterpret_cast<const int4*>(ei + e);
        int4 c4 = *reinterpret_cast<const int4*>(ei + NE + e);
        int p0 = g_beg[c4.x] + atomicAdd(&g_cursor[c4.x], 1);
        int p1 = g_beg[c4.y] + atomicAdd(&g_cursor[c4.y], 1);
        int p2 = g_beg[c4.z] + atomicAdd(&g_cursor[c4.z], 1);
        int p3 = g_beg[c4.w] + atomicAdd(&g_cursor[c4.w], 1);
        g_src[p0] = r4.x; g_wgt[p0] = g_dinv[r4.x] * g_dinv[c4.x];
        g_src[p1] = r4.y; g_wgt[p1] = g_dinv[r4.y] * g_dinv[c4.y];
        g_src[p2] = r4.z; g_wgt[p2] = g_dinv[r4.z] * g_dinv[c4.z];
        g_src[p3] = r4.w; g_wgt[p3] = g_dinv[r4.w] * g_dinv[c4.w];
    } else {
        for (; e < NE; e++) {
            int r = ei[e], c = ei[NE + e];
            int pos = g_beg[c] + atomicAdd(&g_cursor[c], 1);
            g_src[pos] = r;
            g_wgt[pos] = g_dinv[r] * g_dinv[c];
        }
    }
}

// ---- one propagation layer: warp-per-node, gather via fp16 mirror ----
__global__ void __launch_bounds__(256) k_layer(int parity, int layer,
                                               int first, int write_cur) {
    int gw   = (blockIdx.x * blockDim.x + threadIdx.x) >> 5;
    int lane = threadIdx.x & 31;
    if (gw >= NN) return;
    const uint2*  __restrict__ hin  = g_curh[parity];
    const float4* __restrict__ cin  = g_cur[parity];
    float4* __restrict__       cout = g_cur[parity ^ 1];
    uint2*  __restrict__       hout = g_curh[parity ^ 1];

    int beg = g_beg[gw];
    int end = beg + g_cnt[gw];
    float ax = 0.f, ay = 0.f, az = 0.f, aw = 0.f;

    int e = beg;
    for (; e + 3 < end; e += 4) {
        int s0 = g_src[e], s1 = g_src[e + 1], s2 = g_src[e + 2], s3 = g_src[e + 3];
        float w0 = g_wgt[e], w1 = g_wgt[e + 1], w2 = g_wgt[e + 2], w3 = g_wgt[e + 3];
        uint2 p0 = hin[s0 * 32 + lane];
        uint2 p1 = hin[s1 * 32 + lane];
        uint2 p2 = hin[s2 * 32 + lane];
        uint2 p3 = hin[s3 * 32 + lane];
        float2 a0 = __half22float2(*reinterpret_cast<__half2*>(&p0.x));
        float2 b0 = __half22float2(*reinterpret_cast<__half2*>(&p0.y));
        float2 a1 = __half22float2(*reinterpret_cast<__half2*>(&p1.x));
        float2 b1 = __half22float2(*reinterpret_cast<__half2*>(&p1.y));
        float2 a2 = __half22float2(*reinterpret_cast<__half2*>(&p2.x));
        float2 b2 = __half22float2(*reinterpret_cast<__half2*>(&p2.y));
        float2 a3 = __half22float2(*reinterpret_cast<__half2*>(&p3.x));
        float2 b3 = __half22float2(*reinterpret_cast<__half2*>(&p3.y));
        ax = fmaf(w0, a0.x, ax); ay = fmaf(w0, a0.y, ay);
        az = fmaf(w0, b0.x, az); aw = fmaf(w0, b0.y, aw);
        ax = fmaf(w1, a1.x, ax); ay = fmaf(w1, a1.y, ay);
        az = fmaf(w1, b1.x, az); aw = fmaf(w1, b1.y, aw);
        ax = fmaf(w2, a2.x, ax); ay = fmaf(w2, a2.y, ay);
        az = fmaf(w2, b2.x, az); aw = fmaf(w2, b2.y, aw);
        ax = fmaf(w3, a3.x, ax); ay = fmaf(w3, a3.y, ay);
        az = fmaf(w3, b3.x, az); aw = fmaf(w3, b3.y, aw);
    }
    for (; e < end; e++) {
        int s = g_src[e];
        float w = g_wgt[e];
        uint2 p = hin[s * 32 + lane];
        float2 a = __half22float2(*reinterpret_cast<__half2*>(&p.x));
        float2 b = __half22float2(*reinterpret_cast<__half2*>(&p.y));
        ax = fmaf(w, a.x, ax); ay = fmaf(w, a.y, ay);
        az = fmaf(w, b.x, az); aw = fmaf(w, b.y, aw);
    }

    int off = gw * 32 + lane;
    float4 cv = cin[off];   // fp32 carry: no storage-rounding compounding
    float4 o = make_float4(cv.x - ax, cv.y - ay, cv.z - az, cv.w - aw);
    if (write_cur) {
        cout[off] = o;
        hout[off] = pack4h(o.x, o.y, o.z, o.w);
    }

    float tk = g_tk[layer];
    if (first) {
        g_upd[off] = make_float4(tk * o.x, tk * o.y, tk * o.z, tk * o.w);
    } else {
        float4 u = g_upd[off];
        u.x = fmaf(tk, o.x, u.x); u.y = fmaf(tk, o.y, u.y);
        u.z = fmaf(tk, o.z, u.z); u.w = fmaf(tk, o.w, u.w);
        g_upd[off] = u;
    }
}

// ---- epilogue: h = c*upd + (1-c)*x ; out = relu(h @ W^T + b) ----
__global__ void __launch_bounds__(256) k_out(const float4* __restrict__ x4,
                                             const float4* __restrict__ W4,
                                             const float*  __restrict__ bias,
                                             float*        __restrict__ out) {
    __shared__ float sA[32][68];
    __shared__ float sB[32][68];
    int mblk = blockIdx.x * 64;
    int nblk = blockIdx.y * 64;
    int tid = threadIdx.x;
    int tx = tid & 15, ty = tid >> 4;

    float c = g_cst[0], d = 1.f - c;
    float acc[4][4];
#pragma unroll
    for (int i = 0; i < 4; i++)
#pragma unroll
        for (int j = 0; j < 4; j++) acc[i][j] = 0.f;

    for (int k0 = 0; k0 < 128; k0 += 32) {
#pragma unroll
        for (int l = 0; l < 2; l++) {
            int idx = tid + l * 256;
            int m  = idx >> 3;
            int kq = idx & 7;
            int kk = kq * 4;
            int node = mblk + m;
            float4 u  = make_float4(0.f, 0.f, 0.f, 0.f), xv = u;
            if (node < NN) {
                int off = node * 32 + (k0 >> 2) + kq;
                u  = g_upd[off];
                xv = x4[off];
            }
            sA[kk + 0][m] = c * u.x + d * xv.x;
            sA[kk + 1][m] = c * u.y + d * xv.y;
            sA[kk + 2][m] = c * u.z + d * xv.z;
            sA[kk + 3][m] = c * u.w + d * xv.w;
            float4 wv = W4[(nblk + m) * 32 + (k0 >> 2) + kq];
            sB[kk + 0][m] = wv.x;
            sB[kk + 1][m] = wv.y;
            sB[kk + 2][m] = wv.z;
            sB[kk + 3][m] = wv.w;
        }
        __syncthreads();
#pragma unroll
        for (int kk = 0; kk < 32; kk++) {
            float a[4], bb[4];
#pragma unroll
            for (int i = 0; i < 4; i++) a[i] = sA[kk][ty * 4 + i];
#pragma unroll
            for (int j = 0; j < 4; j++) bb[j] = sB[kk][tx * 4 + j];
#pragma unroll
            for (int i = 0; i < 4; i++)
#pragma unroll
                for (int j = 0; j < 4; j++)
                    acc[i][j] = fmaf(a[i], bb[j], acc[i][j]);
        }
        __syncthreads();
    }

#pragma unroll
    for (int i = 0; i < 4; i++) {
        int node = mblk + ty * 4 + i;
        if (node >= NN) continue;
#pragma unroll
        for (int j = 0; j < 4; j++) {
            int jj = nblk + tx * 4 + j;
            float v = acc[i][j] + bias[jj];
            out[node * 128 + jj] = v > 0.f ? v : 0.f;
        }
    }
}

extern "C" void kernel_launch(void* const* d_in, const int* in_sizes, int n_in,
                              void* d_out, int out_size) {
    const float4* x4   = (const float4*)d_in[0];
    const int*    ei   = (const int*)d_in[1];
    const float*  kv   = (const float*)d_in[2];
    const float*  wt   = (const float*)d_in[3];
    const float4* W4   = (const float4*)d_in[4];
    const float*  bias = (const float*)d_in[5];
    float*        out  = (float*)d_out;

    k_init<<<(NF4 + 255) / 256, 256>>>(x4);
    k_count<<<(NE / 4 + 255) / 256, 256>>>(ei);
    k_dinv<<<(NN + 255) / 256, 256>>>(kv, wt);
    k_fill<<<(NE / 4 + 255) / 256, 256>>>(ei);

    int par = 0;
    for (int l = 0; l < 8; l++) {
        k_layer<<<(NN * 32 + 255) / 256, 256>>>(par, l, l == 0, l != 7);
        par ^= 1;
    }

    dim3 g((NN + 63) / 64, 2);
    k_out<<<g, 256>>>(x4, W4, bias, out);
}

// round 9
// speedup vs baseline: 1.3826x; 1.0771x over previous
#include <cuda_runtime.h>
#include <cuda_fp16.h>

#define NN 10000
#define NE 320000
#define NF4 (NN * 32)   // N * 128 floats / 4

// ---- device scratch ----
__device__ int    g_cnt[NN];
__device__ int    g_cursor[NN];
__device__ int    g_beg[NN];
__device__ int    g_total;
__device__ float  g_dinv[NN];
__device__ int2   g_edge[NE];        // {src, wgt-as-int} packed
__device__ float4 g_curS[9][NF4];    // fp32 cur chain: slot 0 = x, slots 1..8 = per-layer
__device__ uint2  g_curh[8][NF4];    // fp16 gather mirrors for slots 0..7
__device__ float  g_tk[8];
__device__ float  g_cst[1];

static __device__ __forceinline__ uint2 pack4h(float a, float b, float c, float d) {
    __half2 lo = __floats2half2_rn(a, b);
    __half2 hi = __floats2half2_rn(c, d);
    uint2 r;
    r.x = *reinterpret_cast<unsigned*>(&lo);
    r.y = *reinterpret_cast<unsigned*>(&hi);
    return r;
}

// ---- init: slot0 = x (fp32 + fp16 mirror), counters = 0 ----
__global__ void k_init(const float4* __restrict__ x4) {
    int i = blockIdx.x * blockDim.x + threadIdx.x;
    if (i < NF4) {
        float4 v = x4[i];
        g_curS[0][i] = v;
        g_curh[0][i] = pack4h(v.x, v.y, v.z, v.w);
    }
    if (i < NN) { g_cnt[i] = 0; g_cursor[i] = 0; }
    if (i == 0) g_total = 0;
}

// ---- degree count over targets: 1 edge/thread (max TLP for atomics) ----
__global__ void k_count(const int* __restrict__ ei) {
    int e = blockIdx.x * blockDim.x + threadIdx.x;
    if (e < NE) atomicAdd(&g_cnt[ei[NE + e]], 1);
}

// ---- dinv = deg^-1/2 (0 -> 1); bucket allocation; scalar prep ----
__global__ void k_dinv(const float* __restrict__ kv, const float* __restrict__ wt) {
    int n = blockIdx.x * blockDim.x + threadIdx.x;
    if (n < NN) {
        int c = g_cnt[n];
        g_dinv[n] = rsqrtf((float)(c ? c : 1));
        g_beg[n] = atomicAdd(&g_total, c);
    }
    if (n < 8)  g_tk[n] = tanhf(kv[n]);
    if (n == 8) g_cst[0] = 1.f / (1.f + expf(-wt[0]));
}

// ---- fill buckets: 1 edge/thread, single packed 8B store ----
__global__ void k_fill(const int* __restrict__ ei) {
    int e = blockIdx.x * blockDim.x + threadIdx.x;
    if (e < NE) {
        int r = ei[e];
        int c = ei[NE + e];
        int pos = g_beg[c] + atomicAdd(&g_cursor[c], 1);
        float w = g_dinv[r] * g_dinv[c];
        g_edge[pos] = make_int2(r, __float_as_int(w));
    }
}

// ---- one propagation layer: warp-per-node, fp16 gather, unroll x8 ----
// reads slot s (fp32 own-row + fp16 gather), writes slot s+1 (+ mirror if s+1<8)
__global__ void __launch_bounds__(256) k_layer(int s) {
    int gw   = (blockIdx.x * blockDim.x + threadIdx.x) >> 5;
    int lane = threadIdx.x & 31;
    if (gw >= NN) return;
    const uint2*  __restrict__ hin  = g_curh[s];
    const float4* __restrict__ cin  = g_curS[s];
    float4* __restrict__       cout = g_curS[s + 1];

    int beg = g_beg[gw];
    int end = beg + g_cnt[gw];
    float ax = 0.f, ay = 0.f, az = 0.f, aw = 0.f;

    int e = beg;
    for (; e + 7 < end; e += 8) {
        int2 e0 = g_edge[e + 0], e1 = g_edge[e + 1], e2 = g_edge[e + 2], e3 = g_edge[e + 3];
        int2 e4 = g_edge[e + 4], e5 = g_edge[e + 5], e6 = g_edge[e + 6], e7 = g_edge[e + 7];
        uint2 p0 = hin[e0.x * 32 + lane];
        uint2 p1 = hin[e1.x * 32 + lane];
        uint2 p2 = hin[e2.x * 32 + lane];
        uint2 p3 = hin[e3.x * 32 + lane];
        uint2 p4 = hin[e4.x * 32 + lane];
        uint2 p5 = hin[e5.x * 32 + lane];
        uint2 p6 = hin[e6.x * 32 + lane];
        uint2 p7 = hin[e7.x * 32 + lane];
#define ACC(P, EV) do {                                                   \
        float w = __int_as_float((EV).y);                                 \
        float2 lo = __half22float2(*reinterpret_cast<__half2*>(&(P).x));  \
        float2 hi = __half22float2(*reinterpret_cast<__half2*>(&(P).y));  \
        ax = fmaf(w, lo.x, ax); ay = fmaf(w, lo.y, ay);                   \
        az = fmaf(w, hi.x, az); aw = fmaf(w, hi.y, aw); } while (0)
        ACC(p0, e0); ACC(p1, e1); ACC(p2, e2); ACC(p3, e3);
        ACC(p4, e4); ACC(p5, e5); ACC(p6, e6); ACC(p7, e7);
    }
    for (; e + 3 < end; e += 4) {
        int2 e0 = g_edge[e + 0], e1 = g_edge[e + 1], e2 = g_edge[e + 2], e3 = g_edge[e + 3];
        uint2 p0 = hin[e0.x * 32 + lane];
        uint2 p1 = hin[e1.x * 32 + lane];
        uint2 p2 = hin[e2.x * 32 + lane];
        uint2 p3 = hin[e3.x * 32 + lane];
        ACC(p0, e0); ACC(p1, e1); ACC(p2, e2); ACC(p3, e3);
    }
    for (; e < end; e++) {
        int2 ev = g_edge[e];
        uint2 p = hin[ev.x * 32 + lane];
        ACC(p, ev);
    }
#undef ACC

    int off = gw * 32 + lane;
    float4 cv = cin[off];   // fp32 carry
    float4 o = make_float4(cv.x - ax, cv.y - ay, cv.z - az, cv.w - aw);
    cout[off] = o;
    if (s + 1 < 8) g_curh[s + 1][off] = pack4h(o.x, o.y, o.z, o.w);
}

// ---- epilogue: u = sum tk_i*cur_{i+1}; h = c*u + (1-c)*x ; relu(h@W^T+b) ----
__global__ void __launch_bounds__(256) k_out(const float4* __restrict__ x4,
                                             const float4* __restrict__ W4,
                                             const float*  __restrict__ bias,
                                             float*        __restrict__ out) {
    __shared__ float sA[32][68];
    __shared__ float sB[32][68];
    int mblk = blockIdx.x * 64;
    int nblk = blockIdx.y * 64;
    int tid = threadIdx.x;
    int tx = tid & 15, ty = tid >> 4;

    float c = g_cst[0], d = 1.f - c;
    float tk[8];
#pragma unroll
    for (int i = 0; i < 8; i++) tk[i] = g_tk[i];

    float acc[4][4];
#pragma unroll
    for (int i = 0; i < 4; i++)
#pragma unroll
        for (int j = 0; j < 4; j++) acc[i][j] = 0.f;

    for (int k0 = 0; k0 < 128; k0 += 32) {
#pragma unroll
        for (int l = 0; l < 2; l++) {
            int idx = tid + l * 256;
            int m  = idx >> 3;
            int kq = idx & 7;
            int kk = kq * 4;
            int node = mblk + m;
            float ux = 0.f, uy = 0.f, uz = 0.f, uw = 0.f;
            float4 xv = make_float4(0.f, 0.f, 0.f, 0.f);
            if (node < NN) {
                int off = node * 32 + (k0 >> 2) + kq;
                xv = x4[off];
#pragma unroll
                for (int i = 0; i < 8; i++) {
                    float4 cv = g_curS[i + 1][off];
                    ux = fmaf(tk[i], cv.x, ux); uy = fmaf(tk[i], cv.y, uy);
                    uz = fmaf(tk[i], cv.z, uz); uw = fmaf(tk[i], cv.w, uw);
                }
            }
            sA[kk + 0][m] = c * ux + d * xv.x;
            sA[kk + 1][m] = c * uy + d * xv.y;
            sA[kk + 2][m] = c * uz + d * xv.z;
            sA[kk + 3][m] = c * uw + d * xv.w;
            float4 wv = W4[(nblk + m) * 32 + (k0 >> 2) + kq];
            sB[kk + 0][m] = wv.x;
            sB[kk + 1][m] = wv.y;
            sB[kk + 2][m] = wv.z;
            sB[kk + 3][m] = wv.w;
        }
        __syncthreads();
#pragma unroll
        for (int kk = 0; kk < 32; kk++) {
            float a[4], bb[4];
#pragma unroll
            for (int i = 0; i < 4; i++) a[i] = sA[kk][ty * 4 + i];
#pragma unroll
            for (int j = 0; j < 4; j++) bb[j] = sB[kk][tx * 4 + j];
#pragma unroll
            for (int i = 0; i < 4; i++)
#pragma unroll
                for (int j = 0; j < 4; j++)
                    acc[i][j] = fmaf(a[i], bb[j], acc[i][j]);
        }
        __syncthreads();
    }

#pragma unroll
    for (int i = 0; i < 4; i++) {
        int node = mblk + ty * 4 + i;
        if (node >= NN) continue;
#pragma unroll
        for (int j = 0; j < 4; j++) {
            int jj = nblk + tx * 4 + j;
            float v = acc[i][j] + bias[jj];
            out[node * 128 + jj] = v > 0.f ? v : 0.f;
        }
    }
}

extern "C" void kernel_launch(void* const* d_in, const int* in_sizes, int n_in,
                              void* d_out, int out_size) {
    const float4* x4   = (const float4*)d_in[0];
    const int*    ei   = (const int*)d_in[1];
    const float*  kv   = (const float*)d_in[2];
    const float*  wt   = (const float*)d_in[3];
    const float4* W4   = (const float4*)d_in[4];
    const float*  bias = (const float*)d_in[5];
    float*        out  = (float*)d_out;

    k_init<<<(NF4 + 255) / 256, 256>>>(x4);
    k_count<<<(NE + 255) / 256, 256>>>(ei);
    k_dinv<<<(NN + 255) / 256, 256>>>(kv, wt);
    k_fill<<<(NE + 255) / 256, 256>>>(ei);

    for (int l = 0; l < 8; l++)
        k_layer<<<(NN * 32 + 255) / 256, 256>>>(l);

    dim3 g((NN + 63) / 64, 2);
    k_out<<<g, 256>>>(x4, W4, bias, out);
}